// round 4
// baseline (speedup 1.0000x reference)
#include <cuda_runtime.h>
#include <cuda_bf16.h>
#include <cstdint>
#include <cstddef>

#define NR 16384
#define DX 1024
#define DH 2048

// ---------------- device scratch (no dynamic allocation allowed) -----------
__device__ __align__(16) __nv_bfloat16 g_X1b[(size_t)NR * DX];
__device__ __align__(16) __nv_bfloat16 g_X2b[(size_t)NR * DX];
__device__ __align__(16) __nv_bfloat16 g_W1h[(size_t)DX * DH];
__device__ __align__(16) __nv_bfloat16 g_W2h[(size_t)DX * DH];
__device__ __align__(16) __nv_bfloat16 g_Wh1[(size_t)DH * DX];
__device__ __align__(16) __nv_bfloat16 g_Wh2[(size_t)DH * DX];
__device__ __align__(16) __nv_bfloat16 g_H1b[(size_t)NR * DH];
__device__ __align__(16) __nv_bfloat16 g_H2b[(size_t)NR * DH];
__device__ float g_row1[NR];
__device__ float g_row2[NR];
__device__ float g_L34[NR];

// ---------------- helpers --------------------------------------------------
__device__ __forceinline__ uint32_t smem_u32(const void* p) {
    uint32_t a;
    asm("{ .reg .u64 t; cvta.to.shared.u64 t, %1; cvt.u32.u64 %0, t; }"
        : "=r"(a) : "l"(p));
    return a;
}
__device__ __forceinline__ void cp16(uint32_t dst, const void* src) {
    uint64_t g;
    asm("cvta.to.global.u64 %0, %1;" : "=l"(g) : "l"(src));
    asm volatile("cp.async.cg.shared.global [%0], [%1], 16;"
                 :: "r"(dst), "l"(g) : "memory");
}
#define CP_COMMIT asm volatile("cp.async.commit_group;" ::: "memory")
#define CP_WAIT(n) asm volatile("cp.async.wait_group %0;" :: "n"(n) : "memory")

// ---------------- converts / init ------------------------------------------
__global__ void f2bf_kernel(const float* __restrict__ src, int sel, int n) {
    __nv_bfloat16* dst;
    switch (sel) {
        case 0: dst = g_X1b; break;  case 1: dst = g_X2b; break;
        case 2: dst = g_W1h; break;  case 3: dst = g_W2h; break;
        case 4: dst = g_Wh1; break;  default: dst = g_Wh2;
    }
    int i = blockIdx.x * blockDim.x + threadIdx.x;
    int stride = gridDim.x * blockDim.x;
    for (int idx = i * 4; idx < n; idx += stride * 4) {
        float4 v = *(const float4*)&src[idx];
        __nv_bfloat162 lo = __floats2bfloat162_rn(v.x, v.y);
        __nv_bfloat162 hi = __floats2bfloat162_rn(v.z, v.w);
        *(uint32_t*)&dst[idx]     = *(uint32_t*)&lo;
        *(uint32_t*)&dst[idx + 2] = *(uint32_t*)&hi;
    }
}
__global__ void zero_rows_kernel() {
    int i = blockIdx.x * blockDim.x + threadIdx.x;
    if (i < NR) { g_row1[i] = 0.f; g_row2[i] = 0.f; }
}

// ---------------- GEMM: C[M,Nout] = A[M,KD] * B[KD,Nout] (+ fused epilogue) --
// EPI=0: Hout = bf16(C + bias).  EPI=1: rowbuf[r] += sum_col (C+bias-Xref)^2
template<int KD, int EPI>
__launch_bounds__(256, 2)
__global__ void gemm_kernel(int cfg, const float* __restrict__ bias,
                            const float* __restrict__ Xref, int Nout) {
    const __nv_bfloat16 *A, *B;
    __nv_bfloat16* Hout = nullptr;
    float* rowbuf = nullptr;
    if (cfg == 0)      { A = g_X1b; B = g_W1h; Hout = g_H1b; }
    else if (cfg == 1) { A = g_X2b; B = g_W2h; Hout = g_H2b; }
    else if (cfg == 2) { A = g_H1b; B = g_Wh2; rowbuf = g_row1; }
    else               { A = g_H2b; B = g_Wh1; rowbuf = g_row2; }

    __shared__ __align__(16) __nv_bfloat16 smA[2][128][40];   // pad 8 -> 80B rows
    __shared__ __align__(16) __nv_bfloat16 smB[2][32][136];   // pad 8 -> 272B rows

    const int tid = threadIdx.x, lane = tid & 31, wid = tid >> 5;
    const int wm = wid >> 2, wn = wid & 3;            // 2 x 4 warp grid
    const int brow = blockIdx.y * 128, bcol = blockIdx.x * 128;

    float c[4][4][4];
    #pragma unroll
    for (int i = 0; i < 4; i++)
        #pragma unroll
        for (int j = 0; j < 4; j++)
            #pragma unroll
            for (int k = 0; k < 4; k++) c[i][j][k] = 0.f;

    auto loadA = [&](int st, int k0) {
        #pragma unroll
        for (int i = 0; i < 2; i++) {
            int id = tid + i * 256;
            int r = id >> 2, kc = (id & 3) * 8;
            cp16(smem_u32(&smA[st][r][kc]),
                 &A[(size_t)(brow + r) * KD + k0 + kc]);
        }
    };
    auto loadB = [&](int st, int k0) {
        #pragma unroll
        for (int i = 0; i < 2; i++) {
            int id = tid + i * 256;
            int r = id >> 4, nc = (id & 15) * 8;
            cp16(smem_u32(&smB[st][r][nc]),
                 &B[(size_t)(k0 + r) * Nout + bcol + nc]);
        }
    };

    loadA(0, 0); loadB(0, 0); CP_COMMIT;
    const int nk = KD / 32;
    for (int kt = 0; kt < nk; kt++) {
        const int cur = kt & 1, nxt = cur ^ 1;
        if (kt + 1 < nk) { loadA(nxt, (kt + 1) * 32); loadB(nxt, (kt + 1) * 32);
                           CP_COMMIT; CP_WAIT(1); }
        else             { CP_WAIT(0); }
        __syncthreads();

        #pragma unroll
        for (int ks = 0; ks < 32; ks += 16) {
            uint32_t a[4][4];
            #pragma unroll
            for (int mt = 0; mt < 4; mt++) {
                uint32_t ad = smem_u32(
                    &smA[cur][wm * 64 + mt * 16 + (lane & 15)][ks + (lane >> 4) * 8]);
                asm volatile(
                    "ldmatrix.sync.aligned.m8n8.x4.shared.b16 {%0,%1,%2,%3},[%4];"
                    : "=r"(a[mt][0]), "=r"(a[mt][1]), "=r"(a[mt][2]), "=r"(a[mt][3])
                    : "r"(ad));
            }
            uint32_t b[2][4];
            #pragma unroll
            for (int np = 0; np < 2; np++) {
                uint32_t ad = smem_u32(
                    &smB[cur][ks + (lane & 15)][wn * 32 + np * 16 + (lane >> 4) * 8]);
                asm volatile(
                    "ldmatrix.sync.aligned.m8n8.x4.trans.shared.b16 {%0,%1,%2,%3},[%4];"
                    : "=r"(b[np][0]), "=r"(b[np][1]), "=r"(b[np][2]), "=r"(b[np][3])
                    : "r"(ad));
            }
            #pragma unroll
            for (int mt = 0; mt < 4; mt++)
                #pragma unroll
                for (int nt = 0; nt < 4; nt++) {
                    uint32_t b0 = b[nt >> 1][(nt & 1) * 2];
                    uint32_t b1 = b[nt >> 1][(nt & 1) * 2 + 1];
                    asm volatile(
                        "mma.sync.aligned.m16n8k16.row.col.f32.bf16.bf16.f32 "
                        "{%0,%1,%2,%3},{%4,%5,%6,%7},{%8,%9},{%0,%1,%2,%3};"
                        : "+f"(c[mt][nt][0]), "+f"(c[mt][nt][1]),
                          "+f"(c[mt][nt][2]), "+f"(c[mt][nt][3])
                        : "r"(a[mt][0]), "r"(a[mt][1]), "r"(a[mt][2]), "r"(a[mt][3]),
                          "r"(b0), "r"(b1));
                }
        }
        __syncthreads();
    }

    // ---------------- fused epilogue ----------------
    if (EPI == 0) {
        #pragma unroll
        for (int mt = 0; mt < 4; mt++) {
            int r0 = brow + wm * 64 + mt * 16 + (lane >> 2);
            #pragma unroll
            for (int nt = 0; nt < 4; nt++) {
                int col = bcol + wn * 32 + nt * 8 + 2 * (lane & 3);
                float b0 = bias[col], b1 = bias[col + 1];
                __nv_bfloat162 v0 = __floats2bfloat162_rn(c[mt][nt][0] + b0,
                                                          c[mt][nt][1] + b1);
                __nv_bfloat162 v1 = __floats2bfloat162_rn(c[mt][nt][2] + b0,
                                                          c[mt][nt][3] + b1);
                *(__nv_bfloat162*)&Hout[(size_t)r0 * Nout + col] = v0;
                *(__nv_bfloat162*)&Hout[(size_t)(r0 + 8) * Nout + col] = v1;
            }
        }
    } else {
        #pragma unroll
        for (int mt = 0; mt < 4; mt++)
            #pragma unroll
            for (int half = 0; half < 2; half++) {
                int r = brow + wm * 64 + mt * 16 + (lane >> 2) + half * 8;
                float s = 0.f;
                #pragma unroll
                for (int nt = 0; nt < 4; nt++) {
                    int col = bcol + wn * 32 + nt * 8 + 2 * (lane & 3);
                    const float* xr = &Xref[(size_t)r * Nout + col];
                    float d0 = c[mt][nt][half * 2 + 0] + bias[col]     - xr[0];
                    float d1 = c[mt][nt][half * 2 + 1] + bias[col + 1] - xr[1];
                    s += d0 * d0 + d1 * d1;
                }
                s += __shfl_xor_sync(0xffffffffu, s, 1);
                s += __shfl_xor_sync(0xffffffffu, s, 2);
                if ((lane & 3) == 0) atomicAdd(&rowbuf[r], s);
            }
    }
}

// ---------------- L3^2 + L4^2 per row --------------------------------------
__global__ void l34_kernel(const float* __restrict__ whoW,
                           const float* __restrict__ whob,
                           const float* __restrict__ Y) {
    int wid = threadIdx.x >> 5, lane = threadIdx.x & 31;
    int r = blockIdx.x * 8 + wid;
    const __nv_bfloat16* h1 = &g_H1b[(size_t)r * DH];
    const __nv_bfloat16* h2 = &g_H2b[(size_t)r * DH];
    float s3 = 0.f, dot = 0.f;
    for (int k = lane * 4; k < DH; k += 128) {
        uint2 u1 = *(const uint2*)&h1[k];
        uint2 u2 = *(const uint2*)&h2[k];
        float4 w = *(const float4*)&whoW[k];
        float2 f1a = __bfloat1622float2(*(__nv_bfloat162*)&u1.x);
        float2 f1b = __bfloat1622float2(*(__nv_bfloat162*)&u1.y);
        float2 f2a = __bfloat1622float2(*(__nv_bfloat162*)&u2.x);
        float2 f2b = __bfloat1622float2(*(__nv_bfloat162*)&u2.y);
        float d;
        d = f1a.x - f2a.x; s3 += d * d; dot += (f1a.x + f2a.x) * w.x;
        d = f1a.y - f2a.y; s3 += d * d; dot += (f1a.y + f2a.y) * w.y;
        d = f1b.x - f2b.x; s3 += d * d; dot += (f1b.x + f2b.x) * w.z;
        d = f1b.y - f2b.y; s3 += d * d; dot += (f1b.y + f2b.y) * w.w;
    }
    #pragma unroll
    for (int o = 16; o; o >>= 1) {
        s3  += __shfl_xor_sync(0xffffffffu, s3, o);
        dot += __shfl_xor_sync(0xffffffffu, dot, o);
    }
    if (lane == 0) {
        float L4 = 0.5f * (dot + whob[0]) - Y[r];
        g_L34[r] = s3 * s3 + L4 * L4;
    }
}

// ---------------- final scalar reduction (double) ---------------------------
__global__ void final_reduce_kernel(float* out) {
    __shared__ double sm[32];
    double s = 0.0;
    for (int r = threadIdx.x; r < NR; r += 1024) {
        double a = (double)g_row1[r], b = (double)g_row2[r];
        s += a * a + b * b + (double)g_L34[r];
    }
    #pragma unroll
    for (int o = 16; o; o >>= 1) s += __shfl_xor_sync(0xffffffffu, s, o);
    if ((threadIdx.x & 31) == 0) sm[threadIdx.x >> 5] = s;
    __syncthreads();
    if (threadIdx.x < 32) {
        double v = sm[threadIdx.x];
        #pragma unroll
        for (int o = 16; o; o >>= 1) v += __shfl_xor_sync(0xffffffffu, v, o);
        if (threadIdx.x == 0) out[0] = (float)v;
    }
}

// ---------------- launch -----------------------------------------------------
extern "C" void kernel_launch(void* const* d_in, const int* in_sizes, int n_in,
                              void* d_out, int out_size) {
    const float* X1   = (const float*)d_in[0];
    const float* X2   = (const float*)d_in[1];
    const float* Y    = (const float*)d_in[2];
    const float* w1hW = (const float*)d_in[3];
    const float* w1hb = (const float*)d_in[4];
    const float* w2hW = (const float*)d_in[5];
    const float* w2hb = (const float*)d_in[6];
    const float* wh1W = (const float*)d_in[7];
    const float* wh1b = (const float*)d_in[8];
    const float* wh2W = (const float*)d_in[9];
    const float* wh2b = (const float*)d_in[10];
    const float* whoW = (const float*)d_in[11];
    const float* whob = (const float*)d_in[12];

    f2bf_kernel<<<1024, 256>>>(X1,   0, NR * DX);
    f2bf_kernel<<<1024, 256>>>(X2,   1, NR * DX);
    f2bf_kernel<<<512,  256>>>(w1hW, 2, DX * DH);
    f2bf_kernel<<<512,  256>>>(w2hW, 3, DX * DH);
    f2bf_kernel<<<512,  256>>>(wh1W, 4, DH * DX);
    f2bf_kernel<<<512,  256>>>(wh2W, 5, DH * DX);
    zero_rows_kernel<<<(NR + 255) / 256, 256>>>();

    dim3 gH(DH / 128, NR / 128);   // (16, 128)
    gemm_kernel<DX, 0><<<gH, 256>>>(0, w1hb, nullptr, DH);
    gemm_kernel<DX, 0><<<gH, 256>>>(1, w2hb, nullptr, DH);
    l34_kernel<<<NR / 8, 256>>>(whoW, whob, Y);

    dim3 gX(DX / 128, NR / 128);   // (8, 128)
    gemm_kernel<DH, 1><<<gX, 256>>>(2, wh2b, X2, DX);
    gemm_kernel<DH, 1><<<gX, 256>>>(3, wh1b, X1, DX);

    final_reduce_kernel<<<1, 1024>>>((float*)d_out);
}